// round 9
// baseline (speedup 1.0000x reference)
#include <cuda_runtime.h>
#include <cuda_bf16.h>

// out[n,:] = x[n,:] * min(1, 1/||x[n,:]||) + noise[n,:]   (L2_NORM_CLIP = 1)
// N = 524288 rows, D = 128 fp32.
// One warp per row: lane i handles float4 chunk i (16B), so each warp touches
// exactly 512 contiguous bytes per tensor -> perfectly coalesced LDG.128/STG.128.

__global__ __launch_bounds__(256) void dp_clip_noise_kernel(
    const float4* __restrict__ x,
    const float4* __restrict__ noise,
    float4* __restrict__ out,
    int nrows)
{
    const int gwarp = (int)((blockIdx.x * blockDim.x + threadIdx.x) >> 5);
    const int lane  = threadIdx.x & 31;
    if (gwarp >= nrows) return;

    // Row `gwarp`, chunk `lane`: D=128 floats = 32 float4 per row.
    const long long idx = (long long)gwarp * 32 + lane;

    // Batch both loads up front (MLP=2 per thread) so DRAM latency overlaps.
    const float4 xv = x[idx];
    const float4 nv = noise[idx];

    // Per-lane partial sum of squares.
    float ssq = xv.x * xv.x + xv.y * xv.y + xv.z * xv.z + xv.w * xv.w;

    // Warp butterfly reduction across 32 lanes -> full-row ||x||^2 in every lane.
    #pragma unroll
    for (int off = 16; off > 0; off >>= 1)
        ssq += __shfl_xor_sync(0xFFFFFFFFu, ssq, off);

    // scale = 1 / max(norm, 1) = min(1, rsqrt(ssq)).  ssq==0 -> rsqrt=+inf -> 1.
    const float scale = fminf(1.0f, rsqrtf(ssq));

    float4 ov;
    ov.x = fmaf(xv.x, scale, nv.x);
    ov.y = fmaf(xv.y, scale, nv.y);
    ov.z = fmaf(xv.z, scale, nv.z);
    ov.w = fmaf(xv.w, scale, nv.w);
    out[idx] = ov;
}

extern "C" void kernel_launch(void* const* d_in, const int* in_sizes, int n_in,
                              void* d_out, int out_size)
{
    const float4* x     = (const float4*)d_in[0];
    const float4* noise = (const float4*)d_in[1];
    float4* out         = (float4*)d_out;

    const int D = 128;
    const int nrows = in_sizes[0] / D;          // 524288

    // One warp per row, 8 warps per 256-thread CTA.
    const int threads = 256;
    const int warps_per_block = threads / 32;
    const int blocks = (nrows + warps_per_block - 1) / warps_per_block;  // 65536

    dp_clip_noise_kernel<<<blocks, threads>>>(x, noise, out, nrows);
}